// round 16
// baseline (speedup 1.0000x reference)
#include <cuda_runtime.h>
#include <math.h>

#define P_MAX  32768
#define NCELLS 4096
#define SORT_BLOCKS  148
#define SORT_THREADS 1024

// ---------------- device scratch (no allocation allowed) --------------------
__device__ int    g_counts[NCELLS];
__device__ int    g_cursor[NCELLS];
__device__ int    g_cell[P_MAX];
__device__ float4 g_pt[P_MAX];    // sorted (x0,x1,x2, bitcast(orig p))
__device__ float4 g_dir[P_MAX];   // sorted (d0,d1,d2, 0)
__device__ unsigned          g_bar_cnt;
__device__ volatile unsigned g_bar_gen;

// ---------------- helpers ---------------------------------------------------
__device__ __forceinline__ int cell_of(float x0, float x1, float x2) {
    float v0 = x0 / 0.1875f + 8.0f;
    float v1 = x1 / 0.1875f + 8.0f;
    float v2 = x2 / 0.1875f + 8.0f;
    int i0 = (int)v0; i0 = min(max(i0, 0), 15);
    int i1 = (int)v1; i1 = min(max(i1, 0), 15);
    int i2 = (int)v2; i2 = min(max(i2, 0), 15);
    return (i0 * 16 + i1) * 16 + i2;
}

__device__ __forceinline__ void gridbar() {
    __syncthreads();
    if (threadIdx.x == 0) {
        unsigned gen = g_bar_gen;
        __threadfence();
        unsigned arrived = atomicAdd(&g_bar_cnt, 1u);
        if (arrived == gridDim.x - 1) {
            g_bar_cnt = 0;
            __threadfence();
            g_bar_gen = gen + 1;
        } else {
            while (g_bar_gen == gen) { __nanosleep(64); }
            __threadfence();
        }
    }
    __syncthreads();
}

__device__ __forceinline__ void pf_l2(const void* p) {
    asm volatile("prefetch.global.L2 [%0];" :: "l"(p));
}

// exactly-1x coverage L2 warm of [base, base+bytes) at 128B granularity
__device__ __forceinline__ void pf_range(const char* base, size_t bytes,
                                         int tid, int nthr) {
    for (size_t off = (size_t)tid * 128; off < bytes; off += (size_t)nthr * 128)
        pf_l2(base + off);
}

// ------- kernel 1: L2 weight warm + counting sort (persistent, wide) --------
__global__ __launch_bounds__(SORT_THREADS) void k_sort(
    const float* __restrict__ x, const float* __restrict__ d,
    const float* __restrict__ l1w, const float* __restrict__ l2w,
    const float* __restrict__ l3w, const float* __restrict__ l4w,
    const float* __restrict__ l5w,
    const float* __restrict__ l1b, const float* __restrict__ l2b,
    const float* __restrict__ l3b, const float* __restrict__ l4b,
    const float* __restrict__ l5b, int P)
{
    int tid  = blockIdx.x * blockDim.x + threadIdx.x;
    int nthr = gridDim.x * blockDim.x;

    // ---- phase -1: stream the ENTIRE weight set into L2 (fire-and-forget) --
    // ~102MB < 126MB L2; finishes during/just after the sort phases below,
    // giving k_mlp's demand loads L2-tier latency instead of DRAM-tier.
    pf_range((const char*)l1w, (size_t)NCELLS * 2016 * 4, tid, nthr);
    pf_range((const char*)l4w, (size_t)NCELLS * 1888 * 4, tid, nthr);
    pf_range((const char*)l2w, (size_t)NCELLS * 1056 * 4, tid, nthr);
    pf_range((const char*)l3w, (size_t)NCELLS * 1024 * 4, tid, nthr);
    pf_range((const char*)l5w, (size_t)NCELLS * 96 * 4, tid, nthr);
    pf_range((const char*)l1b, (size_t)NCELLS * 32 * 4, tid, nthr);
    pf_range((const char*)l2b, (size_t)NCELLS * 33 * 4, tid, nthr);
    pf_range((const char*)l3b, (size_t)NCELLS * 32 * 4, tid, nthr);
    pf_range((const char*)l4b, (size_t)NCELLS * 32 * 4, tid, nthr);
    pf_range((const char*)l5b, (size_t)NCELLS * 3 * 4, tid, nthr);

    // ---- phase 0: zero counts ----
    for (int c = tid; c < NCELLS; c += nthr) g_counts[c] = 0;
    gridbar();

    // ---- phase 1: count ----
    for (int p = tid; p < P; p += nthr) {
        int c = cell_of(x[3 * p], x[3 * p + 1], x[3 * p + 2]);
        g_cell[p] = c;
        atomicAdd(&g_counts[c], 1);
    }
    gridbar();

    // ---- phase 2: exclusive scan (block 0: 1024 thr x 4 cells) ----
    if (blockIdx.x == 0) {
        __shared__ int s[SORT_THREADS];
        int t = threadIdx.x;
        int4 v = ((const int4*)g_counts)[t];
        int sum = v.x + v.y + v.z + v.w;
        s[t] = sum;
        __syncthreads();
        #pragma unroll
        for (int off = 1; off < SORT_THREADS; off <<= 1) {
            int u = (t >= off) ? s[t - off] : 0;
            __syncthreads();
            s[t] += u;
            __syncthreads();
        }
        int base = s[t] - sum;        // exclusive
        g_cursor[4 * t + 0] = base;
        g_cursor[4 * t + 1] = base + v.x;
        g_cursor[4 * t + 2] = base + v.x + v.y;
        g_cursor[4 * t + 3] = base + v.x + v.y + v.z;
    }
    gridbar();

    // ---- phase 3: scatter ----
    for (int p = tid; p < P; p += nthr) {
        int c = g_cell[p];
        int pos = atomicAdd(&g_cursor[c], 1);
        g_pt[pos]  = make_float4(x[3 * p], x[3 * p + 1], x[3 * p + 2], __int_as_float(p));
        g_dir[pos] = make_float4(d[3 * p], d[3 * p + 1], d[3 * p + 2], 0.0f);
    }
}

// ---------------- MLP micro-op: 4 outputs, one float4 load ------------------
__device__ __forceinline__ void fma4(float hv, const float4* __restrict__ w4,
                                     float* __restrict__ acc) {
    float4 a = __ldg(w4);
    acc[0] = fmaf(hv, a.x, acc[0]); acc[1] = fmaf(hv, a.y, acc[1]);
    acc[2] = fmaf(hv, a.z, acc[2]); acc[3] = fmaf(hv, a.w, acc[3]);
}

// ---------------- kernel 2: MLP (8 threads / point, 4 outputs each) ---------
// EXACT R12 body (proven 51.6us) — weights now L2-resident from the warm.
__global__ __launch_bounds__(256, 4) void k_mlp(
    const float* __restrict__ l1w, const float* __restrict__ l1b,
    const float* __restrict__ l2w, const float* __restrict__ l2b,
    const float* __restrict__ l3w, const float* __restrict__ l3b,
    const float* __restrict__ l4w, const float* __restrict__ l4b,
    const float* __restrict__ l5w, const float* __restrict__ l5b,
    float* __restrict__ out, int P)
{
    int t   = blockIdx.x * 256 + threadIdx.x;
    int pi  = t >> 3;
    int sub = t & 7;
    if (pi >= P) return;

    float4 xv = g_pt[pi];
    int p = __float_as_int(xv.w);
    int c = cell_of(xv.x, xv.y, xv.z);
    bool mask = (fabsf(xv.x) < 1.5f) && (fabsf(xv.y) < 1.5f) && (fabsf(xv.z) < 1.5f);
    int lanebase = (threadIdx.x & 31) & ~7;   // lane of sub==0 for this point

    float acc[4], prev[4];

    // ======== layer 1: 63 -> 32, relu — unroll 2 on the j-loop ==============
    {
        const float4* b4 = (const float4*)(l1b + c * 32) + sub;
        float4 b0 = __ldg(b4);
        acc[0] = b0.x; acc[1] = b0.y; acc[2] = b0.z; acc[3] = b0.w;

        const float4* w1 = (const float4*)(l1w + (size_t)c * 2016) + sub;
        fma4(xv.x, w1 + 0 * 8, acc);
        fma4(xv.y, w1 + 1 * 8, acc);
        fma4(xv.z, w1 + 2 * 8, acc);
        float s0 = sinf(xv.x), c0 = cosf(xv.x);
        float s1 = sinf(xv.y), c1 = cosf(xv.y);
        float s2 = sinf(xv.z), c2 = cosf(xv.z);
        #pragma unroll 2
        for (int j = 0; j < 10; j++) {
            const float4* wr = w1 + (3 + 6 * j) * 8;
            fma4(s0, wr + 0 * 8, acc);
            fma4(s1, wr + 1 * 8, acc);
            fma4(s2, wr + 2 * 8, acc);
            fma4(c0, wr + 3 * 8, acc);
            fma4(c1, wr + 4 * 8, acc);
            fma4(c2, wr + 5 * 8, acc);
            float n0 = 2.0f * s0 * c0, m0 = 1.0f - 2.0f * s0 * s0;
            float n1 = 2.0f * s1 * c1, m1 = 1.0f - 2.0f * s1 * s1;
            float n2 = 2.0f * s2 * c2, m2 = 1.0f - 2.0f * s2 * s2;
            s0 = n0; c0 = m0; s1 = n1; c1 = m1; s2 = n2; c2 = m2;
        }
        #pragma unroll
        for (int q = 0; q < 4; q++) prev[q] = fmaxf(acc[q], 0.0f);
    }

    // ======== layer 2: 32 -> 33 (stride 33, scalar), relu; col32 = density ==
    float dens = 0.0f;
    {
        int o0 = sub * 4;
        const float* base = l2w + (size_t)c * 1056 + o0;
        #pragma unroll
        for (int q = 0; q < 4; q++) acc[q] = __ldg(l2b + c * 33 + o0 + q);
        if (sub == 7) dens = __ldg(l2b + c * 33 + 32);
        #pragma unroll 4
        for (int g = 0; g < 8; g++) {
            int src = lanebase + g;
            #pragma unroll
            for (int j = 0; j < 4; j++) {
                float hv = __shfl_sync(0xffffffffu, prev[j], src);
                const float* wr = base + (g * 4 + j) * 33;
                acc[0] = fmaf(hv, __ldg(wr + 0), acc[0]);
                acc[1] = fmaf(hv, __ldg(wr + 1), acc[1]);
                acc[2] = fmaf(hv, __ldg(wr + 2), acc[2]);
                acc[3] = fmaf(hv, __ldg(wr + 3), acc[3]);
                if (sub == 7) dens = fmaf(hv, __ldg(wr + 4), dens);  // o0=28 -> col 32
            }
        }
        dens = fmaxf(dens, 0.0f);
        #pragma unroll
        for (int q = 0; q < 4; q++) { float v = acc[q]; prev[q] = fmaxf(v, 0.0f); }
    }

    // ======== layer 3: 32 -> 32, NO activation ==============================
    {
        const float4* b4 = (const float4*)(l3b + c * 32) + sub;
        float4 b0 = __ldg(b4);
        acc[0] = b0.x; acc[1] = b0.y; acc[2] = b0.z; acc[3] = b0.w;
        const float4* w3 = (const float4*)(l3w + (size_t)c * 1024) + sub;
        #pragma unroll 4
        for (int g = 0; g < 8; g++) {
            int src = lanebase + g;
            #pragma unroll
            for (int j = 0; j < 4; j++) {
                float hv = __shfl_sync(0xffffffffu, prev[j], src);
                fma4(hv, w3 + (g * 4 + j) * 8, acc);
            }
        }
        #pragma unroll
        for (int q = 0; q < 4; q++) prev[q] = acc[q];
    }

    // ======== layer 4: 59 -> 32, relu (32 via shfl + 27 dir, unroll 2) ======
    {
        const float4* b4 = (const float4*)(l4b + c * 32) + sub;
        float4 b0 = __ldg(b4);
        acc[0] = b0.x; acc[1] = b0.y; acc[2] = b0.z; acc[3] = b0.w;
        const float4* w4 = (const float4*)(l4w + (size_t)c * 1888) + sub;
        #pragma unroll 4
        for (int g = 0; g < 8; g++) {
            int src = lanebase + g;
            #pragma unroll
            for (int j = 0; j < 4; j++) {
                float hv = __shfl_sync(0xffffffffu, prev[j], src);
                fma4(hv, w4 + (g * 4 + j) * 8, acc);
            }
        }
        float4 dv = g_dir[pi];
        fma4(dv.x, w4 + 32 * 8, acc);
        fma4(dv.y, w4 + 33 * 8, acc);
        fma4(dv.z, w4 + 34 * 8, acc);
        float s0 = sinf(dv.x), c0 = cosf(dv.x);
        float s1 = sinf(dv.y), c1 = cosf(dv.y);
        float s2 = sinf(dv.z), c2 = cosf(dv.z);
        #pragma unroll 2
        for (int j = 0; j < 4; j++) {
            const float4* wr = w4 + (35 + 6 * j) * 8;
            fma4(s0, wr + 0 * 8, acc);
            fma4(s1, wr + 1 * 8, acc);
            fma4(s2, wr + 2 * 8, acc);
            fma4(c0, wr + 3 * 8, acc);
            fma4(c1, wr + 4 * 8, acc);
            fma4(c2, wr + 5 * 8, acc);
            float n0 = 2.0f * s0 * c0, m0 = 1.0f - 2.0f * s0 * s0;
            float n1 = 2.0f * s1 * c1, m1 = 1.0f - 2.0f * s1 * s1;
            float n2 = 2.0f * s2 * c2, m2 = 1.0f - 2.0f * s2 * s2;
            s0 = n0; c0 = m0; s1 = n1; c1 = m1; s2 = n2; c2 = m2;
        }
        #pragma unroll
        for (int q = 0; q < 4; q++) prev[q] = fmaxf(acc[q], 0.0f);
    }

    // ======== layer 5: 32 -> 3, sigmoid =====================================
    {
        int o = min(sub, 2);
        const float* w5 = l5w + c * 96 + o;
        float a5 = __ldg(l5b + c * 3 + o);
        #pragma unroll 4
        for (int g = 0; g < 8; g++) {
            int src = lanebase + g;
            #pragma unroll
            for (int j = 0; j < 4; j++) {
                float hv = __shfl_sync(0xffffffffu, prev[j], src);
                a5 = fmaf(hv, __ldg(w5 + (g * 4 + j) * 3), a5);
            }
        }
        float cv = 1.0f / (1.0f + expf(-a5));
        if (sub < 3)       out[3 * p + sub] = mask ? cv : 0.0f;
        else if (sub == 7) out[3 * P + p]   = mask ? dens : 0.0f;
    }
}

// ---------------- launch ----------------------------------------------------
extern "C" void kernel_launch(void* const* d_in, const int* in_sizes, int n_in,
                              void* d_out, int out_size) {
    const float* x   = (const float*)d_in[0];
    const float* d   = (const float*)d_in[1];
    const float* l1w = (const float*)d_in[2];
    const float* l1b = (const float*)d_in[3];
    const float* l2w = (const float*)d_in[4];
    const float* l2b = (const float*)d_in[5];
    const float* l3w = (const float*)d_in[6];
    const float* l3b = (const float*)d_in[7];
    const float* l4w = (const float*)d_in[8];
    const float* l4b = (const float*)d_in[9];
    const float* l5w = (const float*)d_in[10];
    const float* l5b = (const float*)d_in[11];
    float* out = (float*)d_out;

    int P = in_sizes[0] / 3;
    if (P > P_MAX) P = P_MAX;

    k_sort<<<SORT_BLOCKS, SORT_THREADS>>>(x, d, l1w, l2w, l3w, l4w, l5w,
                                          l1b, l2b, l3b, l4b, l5b, P);
    int threads = 8 * P;
    k_mlp<<<(threads + 255) / 256, 256>>>(l1w, l1b, l2w, l2b, l3w, l3b,
                                          l4w, l4b, l5w, l5b, out, P);
}

// round 17
// speedup vs baseline: 1.1592x; 1.1592x over previous
#include <cuda_runtime.h>
#include <math.h>

#define P_MAX  32768
#define NCELLS 4096
#define SORT_BLOCKS  148
#define SORT_THREADS 1024

// ---------------- device scratch (no allocation allowed) --------------------
__device__ int    g_counts[NCELLS];   // zeroed by static init (call 1) and k_mlp entry (call n+1)
__device__ int    g_cursor[NCELLS];
__device__ float4 g_pt[P_MAX];    // sorted (x0,x1,x2, bitcast(orig p))
__device__ float4 g_dir[P_MAX];   // sorted (d0,d1,d2, 0)
__device__ unsigned          g_bar_cnt;
__device__ volatile unsigned g_bar_gen;

// ---------------- helpers ---------------------------------------------------
__device__ __forceinline__ int cell_of(float x0, float x1, float x2) {
    float v0 = x0 / 0.1875f + 8.0f;
    float v1 = x1 / 0.1875f + 8.0f;
    float v2 = x2 / 0.1875f + 8.0f;
    int i0 = (int)v0; i0 = min(max(i0, 0), 15);
    int i1 = (int)v1; i1 = min(max(i1, 0), 15);
    int i2 = (int)v2; i2 = min(max(i2, 0), 15);
    return (i0 * 16 + i1) * 16 + i2;
}

__device__ __forceinline__ void gridbar() {
    __syncthreads();
    if (threadIdx.x == 0) {
        unsigned gen = g_bar_gen;
        __threadfence();
        unsigned arrived = atomicAdd(&g_bar_cnt, 1u);
        if (arrived == gridDim.x - 1) {
            g_bar_cnt = 0;
            __threadfence();
            g_bar_gen = gen + 1;
        } else {
            while (g_bar_gen == gen) { __nanosleep(64); }
            __threadfence();
        }
    }
    __syncthreads();
}

// ------- kernel 1: minimal counting sort (registers cached across bar) ------
__global__ __launch_bounds__(SORT_THREADS) void k_sort(
    const float* __restrict__ x, const float* __restrict__ d, int P)
{
    int tid = blockIdx.x * blockDim.x + threadIdx.x;
    // nthr = 151552 > P: each thread owns at most ONE point.

    float x0 = 0.f, x1 = 0.f, x2 = 0.f, d0 = 0.f, d1 = 0.f, d2 = 0.f;
    int c = 0;
    bool have = (tid < P);

    // ---- phase 1: load + count (g_counts arrives zeroed) ----
    if (have) {
        x0 = x[3 * tid]; x1 = x[3 * tid + 1]; x2 = x[3 * tid + 2];
        d0 = d[3 * tid]; d1 = d[3 * tid + 1]; d2 = d[3 * tid + 2];
        c = cell_of(x0, x1, x2);
        atomicAdd(&g_counts[c], 1);
    }
    gridbar();

    // ---- phase 2: exclusive scan (block 0: 1024 thr x 4 cells) ----
    if (blockIdx.x == 0) {
        __shared__ int s[SORT_THREADS];
        int t = threadIdx.x;
        int4 v = ((const int4*)g_counts)[t];
        int sum = v.x + v.y + v.z + v.w;
        s[t] = sum;
        __syncthreads();
        #pragma unroll
        for (int off = 1; off < SORT_THREADS; off <<= 1) {
            int u = (t >= off) ? s[t - off] : 0;
            __syncthreads();
            s[t] += u;
            __syncthreads();
        }
        int base = s[t] - sum;        // exclusive
        g_cursor[4 * t + 0] = base;
        g_cursor[4 * t + 1] = base + v.x;
        g_cursor[4 * t + 2] = base + v.x + v.y;
        g_cursor[4 * t + 3] = base + v.x + v.y + v.z;
    }
    gridbar();

    // ---- phase 3: scatter straight from registers ----
    if (have) {
        int pos = atomicAdd(&g_cursor[c], 1);
        g_pt[pos]  = make_float4(x0, x1, x2, __int_as_float(tid));
        g_dir[pos] = make_float4(d0, d1, d2, 0.0f);
    }
}

// ---------------- MLP micro-op: 4 outputs, one float4 load ------------------
__device__ __forceinline__ void fma4(float hv, const float4* __restrict__ w4,
                                     float* __restrict__ acc) {
    float4 a = __ldg(w4);
    acc[0] = fmaf(hv, a.x, acc[0]); acc[1] = fmaf(hv, a.y, acc[1]);
    acc[2] = fmaf(hv, a.z, acc[2]); acc[3] = fmaf(hv, a.w, acc[3]);
}

// ---------------- kernel 2: MLP (8 threads / point, 4 outputs each) ---------
// EXACT R12 body (proven 51.6us) + counts re-zero at entry for the next call.
__global__ __launch_bounds__(256, 4) void k_mlp(
    const float* __restrict__ l1w, const float* __restrict__ l1b,
    const float* __restrict__ l2w, const float* __restrict__ l2b,
    const float* __restrict__ l3w, const float* __restrict__ l3b,
    const float* __restrict__ l4w, const float* __restrict__ l4b,
    const float* __restrict__ l5w, const float* __restrict__ l5b,
    float* __restrict__ out, int P)
{
    int t   = blockIdx.x * 256 + threadIdx.x;
    // counts are dead after k_sort; re-zero here for the NEXT call
    if (t < NCELLS) g_counts[t] = 0;

    int pi  = t >> 3;
    int sub = t & 7;
    if (pi >= P) return;

    float4 xv = g_pt[pi];
    int p = __float_as_int(xv.w);
    int c = cell_of(xv.x, xv.y, xv.z);
    bool mask = (fabsf(xv.x) < 1.5f) && (fabsf(xv.y) < 1.5f) && (fabsf(xv.z) < 1.5f);
    int lanebase = (threadIdx.x & 31) & ~7;   // lane of sub==0 for this point

    float acc[4], prev[4];

    // ======== layer 1: 63 -> 32, relu — unroll 2 on the j-loop ==============
    {
        const float4* b4 = (const float4*)(l1b + c * 32) + sub;
        float4 b0 = __ldg(b4);
        acc[0] = b0.x; acc[1] = b0.y; acc[2] = b0.z; acc[3] = b0.w;

        const float4* w1 = (const float4*)(l1w + (size_t)c * 2016) + sub;
        fma4(xv.x, w1 + 0 * 8, acc);
        fma4(xv.y, w1 + 1 * 8, acc);
        fma4(xv.z, w1 + 2 * 8, acc);
        float s0 = sinf(xv.x), c0 = cosf(xv.x);
        float s1 = sinf(xv.y), c1 = cosf(xv.y);
        float s2 = sinf(xv.z), c2 = cosf(xv.z);
        #pragma unroll 2
        for (int j = 0; j < 10; j++) {
            const float4* wr = w1 + (3 + 6 * j) * 8;
            fma4(s0, wr + 0 * 8, acc);
            fma4(s1, wr + 1 * 8, acc);
            fma4(s2, wr + 2 * 8, acc);
            fma4(c0, wr + 3 * 8, acc);
            fma4(c1, wr + 4 * 8, acc);
            fma4(c2, wr + 5 * 8, acc);
            float n0 = 2.0f * s0 * c0, m0 = 1.0f - 2.0f * s0 * s0;
            float n1 = 2.0f * s1 * c1, m1 = 1.0f - 2.0f * s1 * s1;
            float n2 = 2.0f * s2 * c2, m2 = 1.0f - 2.0f * s2 * s2;
            s0 = n0; c0 = m0; s1 = n1; c1 = m1; s2 = n2; c2 = m2;
        }
        #pragma unroll
        for (int q = 0; q < 4; q++) prev[q] = fmaxf(acc[q], 0.0f);
    }

    // ======== layer 2: 32 -> 33 (stride 33, scalar), relu; col32 = density ==
    float dens = 0.0f;
    {
        int o0 = sub * 4;
        const float* base = l2w + (size_t)c * 1056 + o0;
        #pragma unroll
        for (int q = 0; q < 4; q++) acc[q] = __ldg(l2b + c * 33 + o0 + q);
        if (sub == 7) dens = __ldg(l2b + c * 33 + 32);
        #pragma unroll 4
        for (int g = 0; g < 8; g++) {
            int src = lanebase + g;
            #pragma unroll
            for (int j = 0; j < 4; j++) {
                float hv = __shfl_sync(0xffffffffu, prev[j], src);
                const float* wr = base + (g * 4 + j) * 33;
                acc[0] = fmaf(hv, __ldg(wr + 0), acc[0]);
                acc[1] = fmaf(hv, __ldg(wr + 1), acc[1]);
                acc[2] = fmaf(hv, __ldg(wr + 2), acc[2]);
                acc[3] = fmaf(hv, __ldg(wr + 3), acc[3]);
                if (sub == 7) dens = fmaf(hv, __ldg(wr + 4), dens);  // o0=28 -> col 32
            }
        }
        dens = fmaxf(dens, 0.0f);
        #pragma unroll
        for (int q = 0; q < 4; q++) { float v = acc[q]; prev[q] = fmaxf(v, 0.0f); }
    }

    // ======== layer 3: 32 -> 32, NO activation ==============================
    {
        const float4* b4 = (const float4*)(l3b + c * 32) + sub;
        float4 b0 = __ldg(b4);
        acc[0] = b0.x; acc[1] = b0.y; acc[2] = b0.z; acc[3] = b0.w;
        const float4* w3 = (const float4*)(l3w + (size_t)c * 1024) + sub;
        #pragma unroll 4
        for (int g = 0; g < 8; g++) {
            int src = lanebase + g;
            #pragma unroll
            for (int j = 0; j < 4; j++) {
                float hv = __shfl_sync(0xffffffffu, prev[j], src);
                fma4(hv, w3 + (g * 4 + j) * 8, acc);
            }
        }
        #pragma unroll
        for (int q = 0; q < 4; q++) prev[q] = acc[q];
    }

    // ======== layer 4: 59 -> 32, relu (32 via shfl + 27 dir, unroll 2) ======
    {
        const float4* b4 = (const float4*)(l4b + c * 32) + sub;
        float4 b0 = __ldg(b4);
        acc[0] = b0.x; acc[1] = b0.y; acc[2] = b0.z; acc[3] = b0.w;
        const float4* w4 = (const float4*)(l4w + (size_t)c * 1888) + sub;
        #pragma unroll 4
        for (int g = 0; g < 8; g++) {
            int src = lanebase + g;
            #pragma unroll
            for (int j = 0; j < 4; j++) {
                float hv = __shfl_sync(0xffffffffu, prev[j], src);
                fma4(hv, w4 + (g * 4 + j) * 8, acc);
            }
        }
        float4 dv = g_dir[pi];
        fma4(dv.x, w4 + 32 * 8, acc);
        fma4(dv.y, w4 + 33 * 8, acc);
        fma4(dv.z, w4 + 34 * 8, acc);
        float s0 = sinf(dv.x), c0 = cosf(dv.x);
        float s1 = sinf(dv.y), c1 = cosf(dv.y);
        float s2 = sinf(dv.z), c2 = cosf(dv.z);
        #pragma unroll 2
        for (int j = 0; j < 4; j++) {
            const float4* wr = w4 + (35 + 6 * j) * 8;
            fma4(s0, wr + 0 * 8, acc);
            fma4(s1, wr + 1 * 8, acc);
            fma4(s2, wr + 2 * 8, acc);
            fma4(c0, wr + 3 * 8, acc);
            fma4(c1, wr + 4 * 8, acc);
            fma4(c2, wr + 5 * 8, acc);
            float n0 = 2.0f * s0 * c0, m0 = 1.0f - 2.0f * s0 * s0;
            float n1 = 2.0f * s1 * c1, m1 = 1.0f - 2.0f * s1 * s1;
            float n2 = 2.0f * s2 * c2, m2 = 1.0f - 2.0f * s2 * s2;
            s0 = n0; c0 = m0; s1 = n1; c1 = m1; s2 = n2; c2 = m2;
        }
        #pragma unroll
        for (int q = 0; q < 4; q++) prev[q] = fmaxf(acc[q], 0.0f);
    }

    // ======== layer 5: 32 -> 3, sigmoid =====================================
    {
        int o = min(sub, 2);
        const float* w5 = l5w + c * 96 + o;
        float a5 = __ldg(l5b + c * 3 + o);
        #pragma unroll 4
        for (int g = 0; g < 8; g++) {
            int src = lanebase + g;
            #pragma unroll
            for (int j = 0; j < 4; j++) {
                float hv = __shfl_sync(0xffffffffu, prev[j], src);
                a5 = fmaf(hv, __ldg(w5 + (g * 4 + j) * 3), a5);
            }
        }
        float cv = 1.0f / (1.0f + expf(-a5));
        if (sub < 3)       out[3 * p + sub] = mask ? cv : 0.0f;
        else if (sub == 7) out[3 * P + p]   = mask ? dens : 0.0f;
    }
}

// ---------------- launch ----------------------------------------------------
extern "C" void kernel_launch(void* const* d_in, const int* in_sizes, int n_in,
                              void* d_out, int out_size) {
    const float* x   = (const float*)d_in[0];
    const float* d   = (const float*)d_in[1];
    const float* l1w = (const float*)d_in[2];
    const float* l1b = (const float*)d_in[3];
    const float* l2w = (const float*)d_in[4];
    const float* l2b = (const float*)d_in[5];
    const float* l3w = (const float*)d_in[6];
    const float* l3b = (const float*)d_in[7];
    const float* l4w = (const float*)d_in[8];
    const float* l4b = (const float*)d_in[9];
    const float* l5w = (const float*)d_in[10];
    const float* l5b = (const float*)d_in[11];
    float* out = (float*)d_out;

    int P = in_sizes[0] / 3;
    if (P > P_MAX) P = P_MAX;

    k_sort<<<SORT_BLOCKS, SORT_THREADS>>>(x, d, P);
    int threads = 8 * P;
    k_mlp<<<(threads + 255) / 256, 256>>>(l1w, l1b, l2w, l2b, l3w, l3b,
                                          l4w, l4b, l5w, l5b, out, P);
}